// round 4
// baseline (speedup 1.0000x reference)
#include <cuda_runtime.h>
#include <cuda_bf16.h>

#define M_LFS      20
#define BLOCK      256
#define TILE_ROWS  256          // rows per tile (1 row/thread)
#define ROW_I4     5            // 20 int32 = 5 int4 = 80B per row
#define TILE_I4    (TILE_ROWS * ROW_I4)   // 1280 int4 = 20KB
#define EPSF       1e-6f

__device__ double       g_acc  = 0.0;
__device__ unsigned int g_done = 0u;

__global__ __launch_bounds__(BLOCK) void ratner_kernel(
    const int*   __restrict__ L,
    const float* __restrict__ alpha,
    const float* __restrict__ beta,
    int n_rows, int n_tiles, int tiles_per_blk,
    float* __restrict__ out, int out_size)
{
    // tab[j*3 + (l+1)] = {f_pos, f_neg} factor pair
    __shared__ float2 tab[M_LFS * 3];
    __shared__ int4   buf[2][TILE_I4];     // double buffer, 2 x 20KB
    __shared__ double dsum[BLOCK / 32];

    const int tid = threadIdx.x;

    if (tid < M_LFS) {
        float a  = 1.0f / (1.0f + expf(-alpha[tid]));
        float b  = beta[tid];
        float ab = 1.0f - b;        // abstain
        float ag = b * a;           // agree
        float dg = b * (1.0f - a);  // disagree
        tab[tid * 3 + 0] = make_float2(dg, ag);   // l == -1
        tab[tid * 3 + 1] = make_float2(ab, ab);   // l ==  0
        tab[tid * 3 + 2] = make_float2(ag, dg);   // l == +1
    }

    long long t0 = (long long)blockIdx.x * tiles_per_blk;
    long long t1 = t0 + tiles_per_blk;
    if (t1 > n_tiles) t1 = n_tiles;

    double acc = 0.0;
    const int4* Lv = (const int4*)L;

    if (t0 < t1) {
        // ---- prologue: fetch tile t0 into registers, stage into buf[0] ----
        int4 r[ROW_I4];
        {
            long long rowbase = t0 * TILE_ROWS;
            int rows = (int)(((long long)n_rows - rowbase < TILE_ROWS)
                                 ? (n_rows - rowbase) : TILE_ROWS);
            int n4 = rows * ROW_I4;
            #pragma unroll
            for (int q = 0; q < ROW_I4; q++) {
                int idx = q * BLOCK + tid;          // lane-consecutive -> coalesced
                r[q] = (idx < n4) ? Lv[rowbase * ROW_I4 + idx]
                                  : make_int4(0, 0, 0, 0);
            }
            #pragma unroll
            for (int q = 0; q < ROW_I4; q++)
                buf[0][q * BLOCK + tid] = r[q];
        }

        for (long long tile = t0; tile < t1; ++tile) {
            int cur = (int)((tile - t0) & 1);
            long long rowbase = tile * TILE_ROWS;
            int rows = (int)(((long long)n_rows - rowbase < TILE_ROWS)
                                 ? (n_rows - rowbase) : TILE_ROWS);

            // ---- issue next tile's global loads early (latency overlap) ----
            bool have_next = (tile + 1 < t1);
            if (have_next) {
                long long nb = (tile + 1) * TILE_ROWS;
                int nrows = (int)(((long long)n_rows - nb < TILE_ROWS)
                                      ? (n_rows - nb) : TILE_ROWS);
                int n4 = nrows * ROW_I4;
                #pragma unroll
                for (int q = 0; q < ROW_I4; q++) {
                    int idx = q * BLOCK + tid;
                    r[q] = (idx < n4) ? Lv[nb * ROW_I4 + idx]
                                      : make_int4(0, 0, 0, 0);
                }
            }

            __syncthreads();   // buf[cur] stores from previous iteration visible

            // ---- compute one row from SMEM (conflict-free LDS.128) ----
            if (tid < rows) {
                int4 v0 = buf[cur][tid * ROW_I4 + 0];
                int4 v1 = buf[cur][tid * ROW_I4 + 1];
                int4 v2 = buf[cur][tid * ROW_I4 + 2];
                int4 v3 = buf[cur][tid * ROW_I4 + 3];
                int4 v4 = buf[cur][tid * ROW_I4 + 4];
                int lv[M_LFS] = { v0.x, v0.y, v0.z, v0.w,
                                  v1.x, v1.y, v1.z, v1.w,
                                  v2.x, v2.y, v2.z, v2.w,
                                  v3.x, v3.y, v3.z, v3.w,
                                  v4.x, v4.y, v4.z, v4.w };
                float pp = 1.0f, pn = 1.0f;
                #pragma unroll
                for (int j = 0; j < M_LFS; j++) {
                    float2 t = tab[j * 3 + (lv[j] + 1)];
                    pp *= t.x;
                    pn *= t.y;
                }
                acc += (double)__logf(pp + pn + EPSF);
            }

            // ---- stage next tile into the other buffer ----
            if (have_next) {
                #pragma unroll
                for (int q = 0; q < ROW_I4; q++)
                    buf[1 - cur][q * BLOCK + tid] = r[q];
            }
        }
    }

    // ---- reduction: warp shuffle (double) -> block -> global atomic ----
    #pragma unroll
    for (int off = 16; off > 0; off >>= 1)
        acc += __shfl_xor_sync(0xFFFFFFFFu, acc, off);

    int lane = tid & 31, warp = tid >> 5;
    if (lane == 0) dsum[warp] = acc;
    __syncthreads();

    if (warp == 0) {
        double s = (lane < BLOCK / 32) ? dsum[lane] : 0.0;
        #pragma unroll
        for (int off = 4; off > 0; off >>= 1)
            s += __shfl_xor_sync(0xFFFFFFFFu, s, off);
        if (lane == 0) {
            atomicAdd(&g_acc, s);
            __threadfence();
            unsigned int ticket = atomicAdd(&g_done, 1u);
            if (ticket == gridDim.x - 1) {
                // last block: finalize + reset for the next graph replay
                double v = atomicAdd(&g_acc, 0.0);
                float res = (float)(-v);
                for (int i = 0; i < out_size; i++) out[i] = res;
                g_acc = 0.0;
                __threadfence();
                g_done = 0u;
            }
        }
    }
}

extern "C" void kernel_launch(void* const* d_in, const int* in_sizes, int n_in,
                              void* d_out, int out_size) {
    const int*   L     = (const int*)d_in[0];
    const float* alpha = (const float*)d_in[1];
    const float* beta  = (const float*)d_in[2];
    float*       out   = (float*)d_out;

    int n_rows  = in_sizes[0] / M_LFS;
    int n_tiles = (n_rows + TILE_ROWS - 1) / TILE_ROWS;

    // target ~5 resident blocks x 152 SMs; contiguous tile partition
    int target_blocks = 760;
    if (target_blocks > n_tiles) target_blocks = n_tiles;
    int tiles_per_blk = (n_tiles + target_blocks - 1) / target_blocks;
    int n_blocks      = (n_tiles + tiles_per_blk - 1) / tiles_per_blk;

    ratner_kernel<<<n_blocks, BLOCK>>>(L, alpha, beta,
                                       n_rows, n_tiles, tiles_per_blk,
                                       out, out_size);
}

// round 5
// speedup vs baseline: 1.6654x; 1.6654x over previous
#include <cuda_runtime.h>
#include <cuda_bf16.h>
#include <cstdint>

#define M_LFS      20
#define BLOCK      256
#define TILE_ROWS  256                       // 1 row per thread per tile
#define ROW_BYTES  80                        // 20 x int32
#define TILE_BYTES (TILE_ROWS * ROW_BYTES)   // 20480, multiple of 16
#define NSTAGES    4
#define N_PAIRS    (M_LFS / 2)               // 10
#define EPSF       1e-6f

__device__ double       g_acc  = 0.0;
__device__ unsigned int g_done = 0u;

extern __shared__ __align__(128) unsigned char smem_dyn[];   // NSTAGES * TILE_BYTES

__device__ __forceinline__ uint32_t smem_u32(const void* p) {
    uint32_t a;
    asm("{ .reg .u64 t; cvta.to.shared.u64 t, %1; cvt.u32.u64 %0, t; }"
        : "=r"(a) : "l"(p));
    return a;
}

__device__ __forceinline__ void mbar_init(uint32_t addr, uint32_t count) {
    asm volatile("mbarrier.init.shared::cta.b64 [%0], %1;" :: "r"(addr), "r"(count) : "memory");
}

__device__ __forceinline__ void mbar_arrive(uint32_t addr) {
    asm volatile("mbarrier.arrive.release.cta.shared::cta.b64 _, [%0];" :: "r"(addr) : "memory");
}

__device__ __forceinline__ void mbar_expect_tx(uint32_t addr, uint32_t bytes) {
    asm volatile("mbarrier.arrive.expect_tx.shared::cta.b64 _, [%0], %1;"
                 :: "r"(addr), "r"(bytes) : "memory");
}

__device__ __forceinline__ void mbar_wait(uint32_t addr, uint32_t parity) {
    asm volatile(
        "{\n\t"
        ".reg .pred P;\n\t"
        "WAITLOOP_%=:\n\t"
        "mbarrier.try_wait.parity.acquire.cta.shared::cta.b64 P, [%0], %1, 0x989680;\n\t"
        "@!P bra WAITLOOP_%=;\n\t"
        "}"
        :: "r"(addr), "r"(parity) : "memory");
}

__device__ __forceinline__ void bulk_copy_g2s(uint32_t dst_smem, const void* src_gmem,
                                              uint32_t bytes, uint32_t mbar) {
    asm volatile(
        "cp.async.bulk.shared::cta.global.mbarrier::complete_tx::bytes [%0], [%1], %2, [%3];"
        :: "r"(dst_smem), "l"(src_gmem), "r"(bytes), "r"(mbar) : "memory");
}

__global__ __launch_bounds__(BLOCK) void ratner_kernel(
    const int*   __restrict__ L,
    const float* __restrict__ alpha,
    const float* __restrict__ beta,
    int n_rows, int n_tiles, int tiles_per_blk,
    float* __restrict__ out, int out_size)
{
    // Pair table: tab2[p*9 + (3*la + lb + 4)] = (f_pos(j0,la)*f_pos(j1,lb),
    //                                            f_neg(j0,la)*f_neg(j1,lb))
    __shared__ float2 tab2[N_PAIRS * 9];
    __shared__ unsigned long long mbar_full_s[NSTAGES];
    __shared__ unsigned long long mbar_empty_s[NSTAGES];
    __shared__ double dsum[BLOCK / 32];

    const int tid = threadIdx.x;

    // ---- build pair lookup table (90 entries) ----
    if (tid < N_PAIRS * 9) {
        int p = tid / 9, c = tid % 9;
        int la = c / 3 - 1, lb = c % 3 - 1;
        int j0 = 2 * p, j1 = 2 * p + 1;

        float a0 = 1.0f / (1.0f + expf(-alpha[j0]));
        float b0 = beta[j0];
        float a1 = 1.0f / (1.0f + expf(-alpha[j1]));
        float b1 = beta[j1];

        float fp0 = (la == 0) ? (1.0f - b0) : ((la == 1) ? b0 * a0 : b0 * (1.0f - a0));
        float fn0 = (la == 0) ? (1.0f - b0) : ((la == 1) ? b0 * (1.0f - a0) : b0 * a0);
        float fp1 = (lb == 0) ? (1.0f - b1) : ((lb == 1) ? b1 * a1 : b1 * (1.0f - a1));
        float fn1 = (lb == 0) ? (1.0f - b1) : ((lb == 1) ? b1 * (1.0f - a1) : b1 * a1);

        tab2[tid] = make_float2(fp0 * fp1, fn0 * fn1);
    }

    // ---- init mbarriers ----
    uint32_t full_b[NSTAGES], empty_b[NSTAGES];
    #pragma unroll
    for (int s = 0; s < NSTAGES; s++) {
        full_b[s]  = smem_u32(&mbar_full_s[s]);
        empty_b[s] = smem_u32(&mbar_empty_s[s]);
    }
    if (tid == 0) {
        #pragma unroll
        for (int s = 0; s < NSTAGES; s++) {
            mbar_init(full_b[s], 1);        // producer's expect_tx arrive
            mbar_init(empty_b[s], BLOCK);   // every thread arrives per tile
        }
    }
    asm volatile("fence.proxy.async.shared::cta;" ::: "memory");
    __syncthreads();

    uint32_t buf_base = smem_u32(smem_dyn);

    long long t0 = (long long)blockIdx.x * tiles_per_blk;
    long long t1 = t0 + tiles_per_blk;
    if (t1 > n_tiles) t1 = n_tiles;
    int my_tiles = (int)(t1 - t0);

    double acc = 0.0;

    if (my_tiles > 0) {
        // ---- producer prologue: fill up to NSTAGES stages ----
        if (tid == 0) {
            int np = my_tiles < NSTAGES ? my_tiles : NSTAGES;
            for (int s = 0; s < np; s++) {
                long long tile = t0 + s;
                long long rowbase = tile * TILE_ROWS;
                int rows = (int)((n_rows - rowbase < TILE_ROWS) ? (n_rows - rowbase) : TILE_ROWS);
                uint32_t bytes = (uint32_t)rows * ROW_BYTES;
                mbar_expect_tx(full_b[s], bytes);
                bulk_copy_g2s(buf_base + s * TILE_BYTES,
                              (const char*)L + rowbase * ROW_BYTES,
                              bytes, full_b[s]);
            }
        }

        for (int i = 0; i < my_tiles; i++) {
            int s  = i & (NSTAGES - 1);
            uint32_t ph = (uint32_t)((i >> 2) & 1);

            mbar_wait(full_b[s], ph);

            long long rowbase = (t0 + i) * TILE_ROWS;
            int rows = (int)((n_rows - rowbase < TILE_ROWS) ? (n_rows - rowbase) : TILE_ROWS);

            if (tid < rows) {
                const int4* rowp =
                    (const int4*)(smem_dyn + s * TILE_BYTES + tid * ROW_BYTES);
                int4 v0 = rowp[0], v1 = rowp[1], v2 = rowp[2], v3 = rowp[3], v4 = rowp[4];
                int lv[M_LFS] = { v0.x, v0.y, v0.z, v0.w,
                                  v1.x, v1.y, v1.z, v1.w,
                                  v2.x, v2.y, v2.z, v2.w,
                                  v3.x, v3.y, v3.z, v3.w,
                                  v4.x, v4.y, v4.z, v4.w };
                float pp = 1.0f, pn = 1.0f;
                #pragma unroll
                for (int p = 0; p < N_PAIRS; p++) {
                    int c = lv[2 * p] * 3 + lv[2 * p + 1] + 4;   // 0..8
                    float2 f = tab2[p * 9 + c];
                    pp *= f.x;
                    pn *= f.y;
                }
                acc += (double)__logf(pp + pn + EPSF);
            }

            mbar_arrive(empty_b[s]);

            // ---- producer: refill this stage with tile i+NSTAGES ----
            if (tid == 0 && i + NSTAGES < my_tiles) {
                mbar_wait(empty_b[s], ph);   // all 256 consumed tile i
                long long tile2 = t0 + i + NSTAGES;
                long long rb2 = tile2 * TILE_ROWS;
                int rows2 = (int)((n_rows - rb2 < TILE_ROWS) ? (n_rows - rb2) : TILE_ROWS);
                uint32_t bytes2 = (uint32_t)rows2 * ROW_BYTES;
                mbar_expect_tx(full_b[s], bytes2);
                bulk_copy_g2s(buf_base + s * TILE_BYTES,
                              (const char*)L + rb2 * ROW_BYTES,
                              bytes2, full_b[s]);
            }
        }
    }

    // ---- reduction: warp (double) -> block -> global atomic ----
    #pragma unroll
    for (int off = 16; off > 0; off >>= 1)
        acc += __shfl_xor_sync(0xFFFFFFFFu, acc, off);

    int lane = tid & 31, warp = tid >> 5;
    if (lane == 0) dsum[warp] = acc;
    __syncthreads();

    if (warp == 0) {
        double sv = (lane < BLOCK / 32) ? dsum[lane] : 0.0;
        #pragma unroll
        for (int off = 4; off > 0; off >>= 1)
            sv += __shfl_xor_sync(0xFFFFFFFFu, sv, off);
        if (lane == 0) {
            atomicAdd(&g_acc, sv);
            __threadfence();
            unsigned int ticket = atomicAdd(&g_done, 1u);
            if (ticket == gridDim.x - 1) {
                double v = atomicAdd(&g_acc, 0.0);
                float res = (float)(-v);
                for (int i = 0; i < out_size; i++) out[i] = res;
                g_acc = 0.0;
                __threadfence();
                g_done = 0u;
            }
        }
    }
}

extern "C" void kernel_launch(void* const* d_in, const int* in_sizes, int n_in,
                              void* d_out, int out_size) {
    const int*   L     = (const int*)d_in[0];
    const float* alpha = (const float*)d_in[1];
    const float* beta  = (const float*)d_in[2];
    float*       out   = (float*)d_out;

    int n_rows  = in_sizes[0] / M_LFS;
    int n_tiles = (n_rows + TILE_ROWS - 1) / TILE_ROWS;

    size_t dyn_smem = (size_t)NSTAGES * TILE_BYTES;   // 81920 B
    cudaFuncSetAttribute(ratner_kernel,
                         cudaFuncAttributeMaxDynamicSharedMemorySize,
                         (int)dyn_smem);

    // ~2 resident blocks per SM on 152-SM GB300
    int target_blocks = 304;
    if (target_blocks > n_tiles) target_blocks = n_tiles;
    int tiles_per_blk = (n_tiles + target_blocks - 1) / target_blocks;
    int n_blocks      = (n_tiles + tiles_per_blk - 1) / tiles_per_blk;

    ratner_kernel<<<n_blocks, BLOCK, dyn_smem>>>(L, alpha, beta,
                                                 n_rows, n_tiles, tiles_per_blk,
                                                 out, out_size);
}

// round 8
// speedup vs baseline: 1.7395x; 1.0445x over previous
#include <cuda_runtime.h>
#include <cuda_bf16.h>
#include <cstdint>

#define M_LFS      20
#define N_CONSUMER 256                       // consumer threads (8 warps)
#define BLOCK      288                       // + 1 producer warp
#define TILE_ROWS  256                       // 1 row per consumer thread
#define ROW_BYTES  80                        // 20 x int32
#define TILE_BYTES (TILE_ROWS * ROW_BYTES)   // 20480
#define NSTAGES    4
#define N_PAIRS    (M_LFS / 2)               // 10
#define EPSF       1e-6f

__device__ double       g_acc  = 0.0;
__device__ unsigned int g_done = 0u;

extern __shared__ __align__(128) unsigned char smem_dyn[];   // NSTAGES * TILE_BYTES

__device__ __forceinline__ uint32_t smem_u32(const void* p) {
    uint32_t a;
    asm("{ .reg .u64 t; cvta.to.shared.u64 t, %1; cvt.u32.u64 %0, t; }"
        : "=r"(a) : "l"(p));
    return a;
}

__device__ __forceinline__ void mbar_init(uint32_t addr, uint32_t count) {
    asm volatile("mbarrier.init.shared::cta.b64 [%0], %1;" :: "r"(addr), "r"(count) : "memory");
}

__device__ __forceinline__ void mbar_arrive(uint32_t addr) {
    asm volatile("mbarrier.arrive.release.cta.shared::cta.b64 _, [%0];" :: "r"(addr) : "memory");
}

__device__ __forceinline__ void mbar_expect_tx(uint32_t addr, uint32_t bytes) {
    asm volatile("mbarrier.arrive.expect_tx.shared::cta.b64 _, [%0], %1;"
                 :: "r"(addr), "r"(bytes) : "memory");
}

__device__ __forceinline__ void mbar_wait(uint32_t addr, uint32_t parity) {
    asm volatile(
        "{\n\t"
        ".reg .pred P;\n\t"
        "WAITLOOP_%=:\n\t"
        "mbarrier.try_wait.parity.acquire.cta.shared::cta.b64 P, [%0], %1, 0x989680;\n\t"
        "@!P bra WAITLOOP_%=;\n\t"
        "}"
        :: "r"(addr), "r"(parity) : "memory");
}

// Relaxed wait for the producer: post-wait SMEM access is async-proxy (TMA) only.
__device__ __forceinline__ void mbar_wait_relaxed(uint32_t addr, uint32_t parity) {
    asm volatile(
        "{\n\t"
        ".reg .pred P;\n\t"
        "WAITLOOP_%=:\n\t"
        "mbarrier.try_wait.parity.relaxed.cta.shared::cta.b64 P, [%0], %1, 0x989680;\n\t"
        "@!P bra WAITLOOP_%=;\n\t"
        "}"
        :: "r"(addr), "r"(parity) : "memory");
}

__device__ __forceinline__ void bulk_copy_g2s(uint32_t dst_smem, const void* src_gmem,
                                              uint32_t bytes, uint32_t mbar) {
    asm volatile(
        "cp.async.bulk.shared::cta.global.mbarrier::complete_tx::bytes [%0], [%1], %2, [%3];"
        :: "r"(dst_smem), "l"(src_gmem), "r"(bytes), "r"(mbar) : "memory");
}

__global__ __launch_bounds__(BLOCK) void ratner_kernel(
    const int*   __restrict__ L,
    const float* __restrict__ alpha,
    const float* __restrict__ beta,
    int n_rows, int n_tiles, int tiles_per_blk,
    float* __restrict__ out, int out_size)
{
    // Pair table: tab2[p*9 + (3*la + lb + 4)] = (f_pos0*f_pos1, f_neg0*f_neg1)
    __shared__ float2 tab2[N_PAIRS * 9];
    __shared__ unsigned long long mbar_full_s[NSTAGES];
    __shared__ unsigned long long mbar_empty_s[NSTAGES];
    __shared__ double dsum[BLOCK / 32];

    const int tid  = threadIdx.x;
    const int lane = tid & 31;
    const int warp = tid >> 5;                // 0..7 consumers, 8 producer

    // ---- build pair lookup table (90 entries) ----
    if (tid < N_PAIRS * 9) {
        int p = tid / 9, c = tid % 9;
        int la = c / 3 - 1, lb = c % 3 - 1;
        int j0 = 2 * p, j1 = 2 * p + 1;

        float a0 = 1.0f / (1.0f + expf(-alpha[j0]));
        float b0 = beta[j0];
        float a1 = 1.0f / (1.0f + expf(-alpha[j1]));
        float b1 = beta[j1];

        float fp0 = (la == 0) ? (1.0f - b0) : ((la == 1) ? b0 * a0 : b0 * (1.0f - a0));
        float fn0 = (la == 0) ? (1.0f - b0) : ((la == 1) ? b0 * (1.0f - a0) : b0 * a0);
        float fp1 = (lb == 0) ? (1.0f - b1) : ((lb == 1) ? b1 * a1 : b1 * (1.0f - a1));
        float fn1 = (lb == 0) ? (1.0f - b1) : ((lb == 1) ? b1 * (1.0f - a1) : b1 * a1);

        tab2[tid] = make_float2(fp0 * fp1, fn0 * fn1);
    }

    uint32_t full_b[NSTAGES], empty_b[NSTAGES];
    #pragma unroll
    for (int s = 0; s < NSTAGES; s++) {
        full_b[s]  = smem_u32(&mbar_full_s[s]);
        empty_b[s] = smem_u32(&mbar_empty_s[s]);
    }
    if (tid == 0) {
        #pragma unroll
        for (int s = 0; s < NSTAGES; s++) {
            mbar_init(full_b[s], 1);    // producer expect_tx arrive
            mbar_init(empty_b[s], 8);   // one elected arrive per consumer warp
        }
    }
    asm volatile("fence.proxy.async.shared::cta;" ::: "memory");
    __syncthreads();

    uint32_t buf_base = smem_u32(smem_dyn);

    long long t0 = (long long)blockIdx.x * tiles_per_blk;
    long long t1 = t0 + tiles_per_blk;
    if (t1 > n_tiles) t1 = n_tiles;
    int my_tiles = (int)(t1 - t0);

    float facc = 0.0f;

    if (warp == 8) {
        // ================= producer warp =================
        if (lane == 0) {
            for (int j = 0; j < my_tiles; j++) {
                int s = j & (NSTAGES - 1);
                if (j >= NSTAGES)
                    mbar_wait_relaxed(empty_b[s], ((j - NSTAGES) >> 2) & 1);
                long long rowbase = (t0 + j) * TILE_ROWS;
                int rows = (int)((n_rows - rowbase < TILE_ROWS)
                                     ? (n_rows - rowbase) : TILE_ROWS);
                uint32_t bytes = (uint32_t)rows * ROW_BYTES;
                mbar_expect_tx(full_b[s], bytes);
                bulk_copy_g2s(buf_base + s * TILE_BYTES,
                              (const char*)L + rowbase * ROW_BYTES,
                              bytes, full_b[s]);
            }
        }
    } else {
        // ================= consumer warps (0..7) =================
        for (int i = 0; i < my_tiles; i++) {
            int s = i & (NSTAGES - 1);
            mbar_wait(full_b[s], (i >> 2) & 1);

            long long rowbase = (t0 + i) * TILE_ROWS;
            int rows = (int)((n_rows - rowbase < TILE_ROWS)
                                 ? (n_rows - rowbase) : TILE_ROWS);

            if (tid < rows) {
                const int4* rowp =
                    (const int4*)(smem_dyn + s * TILE_BYTES + tid * ROW_BYTES);
                int4 v0 = rowp[0], v1 = rowp[1], v2 = rowp[2], v3 = rowp[3], v4 = rowp[4];
                int lv[M_LFS] = { v0.x, v0.y, v0.z, v0.w,
                                  v1.x, v1.y, v1.z, v1.w,
                                  v2.x, v2.y, v2.z, v2.w,
                                  v3.x, v3.y, v3.z, v3.w,
                                  v4.x, v4.y, v4.z, v4.w };
                float pp = 1.0f, pn = 1.0f;
                #pragma unroll
                for (int p = 0; p < N_PAIRS; p++) {
                    int c = lv[2 * p] * 3 + lv[2 * p + 1] + 4;   // 0..8
                    float2 f = tab2[p * 9 + c];
                    pp *= f.x;
                    pn *= f.y;
                }
                facc += __logf(pp + pn + EPSF);
            }

            __syncwarp();
            if (lane == 0) mbar_arrive(empty_b[s]);
        }
    }

    // ---- reduction: warp (double) -> block -> global atomic ----
    double acc = (double)facc;
    #pragma unroll
    for (int off = 16; off > 0; off >>= 1)
        acc += __shfl_xor_sync(0xFFFFFFFFu, acc, off);

    if (lane == 0) dsum[warp] = acc;
    __syncthreads();

    if (warp == 0) {
        double sv = (lane < BLOCK / 32) ? dsum[lane] : 0.0;
        #pragma unroll
        for (int off = 8; off > 0; off >>= 1)
            sv += __shfl_xor_sync(0xFFFFFFFFu, sv, off);
        if (lane == 0) {
            atomicAdd(&g_acc, sv);
            __threadfence();
            unsigned int ticket = atomicAdd(&g_done, 1u);
            if (ticket == gridDim.x - 1) {
                double v = atomicAdd(&g_acc, 0.0);
                float res = (float)(-v);
                for (int i = 0; i < out_size; i++) out[i] = res;
                g_acc = 0.0;
                __threadfence();
                g_done = 0u;
            }
        }
    }
}

extern "C" void kernel_launch(void* const* d_in, const int* in_sizes, int n_in,
                              void* d_out, int out_size) {
    const int*   L     = (const int*)d_in[0];
    const float* alpha = (const float*)d_in[1];
    const float* beta  = (const float*)d_in[2];
    float*       out   = (float*)d_out;

    int n_rows  = in_sizes[0] / M_LFS;
    int n_tiles = (n_rows + TILE_ROWS - 1) / TILE_ROWS;

    size_t dyn_smem = (size_t)NSTAGES * TILE_BYTES;   // 81920 B
    cudaFuncSetAttribute(ratner_kernel,
                         cudaFuncAttributeMaxDynamicSharedMemorySize,
                         (int)dyn_smem);

    // 2 resident blocks per SM on 152-SM GB300
    int target_blocks = 304;
    if (target_blocks > n_tiles) target_blocks = n_tiles;
    int tiles_per_blk = (n_tiles + target_blocks - 1) / target_blocks;
    int n_blocks      = (n_tiles + tiles_per_blk - 1) / tiles_per_blk;

    ratner_kernel<<<n_blocks, BLOCK, dyn_smem>>>(L, alpha, beta,
                                                 n_rows, n_tiles, tiles_per_blk,
                                                 out, out_size);
}